// round 8
// baseline (speedup 1.0000x reference)
#include <cuda_runtime.h>
#include <cstdint>

// Problem constants (fixed shapes)
#define BB 4
#define NN 2048
#define DM 1024
#define HH 16
#define DH 64
#define NPHYS 8
#define M_ROWS (BB * NN)          // 8192
#define QKV_COLS (3 * DM)         // 3072

__device__ float g_qkv[(size_t)M_ROWS * QKV_COLS];  // [B*N, 3D]
__device__ float g_att[(size_t)M_ROWS * DM];        // [B*N, D]

__device__ __forceinline__ uint32_t f2tf32(float x) {
    uint32_t r;
    asm("cvt.rna.tf32.f32 %0, %1;" : "=r"(r) : "f"(x));
    return r;
}

__device__ __forceinline__ void mma_tf32(float* c, const uint32_t* a, const uint32_t* b) {
    asm volatile(
        "mma.sync.aligned.m16n8k8.row.col.f32.tf32.tf32.f32 "
        "{%0,%1,%2,%3}, {%4,%5,%6,%7}, {%8,%9}, {%0,%1,%2,%3};"
        : "+f"(c[0]), "+f"(c[1]), "+f"(c[2]), "+f"(c[3])
        : "r"(a[0]), "r"(a[1]), "r"(a[2]), "r"(a[3]), "r"(b[0]), "r"(b[1]));
}

__device__ __forceinline__ void ldsm_x4(uint32_t& r0, uint32_t& r1, uint32_t& r2,
                                        uint32_t& r3, uint32_t addr) {
    asm volatile("ldmatrix.sync.aligned.m8n8.x4.shared.b16 {%0,%1,%2,%3}, [%4];"
                 : "=r"(r0), "=r"(r1), "=r"(r2), "=r"(r3) : "r"(addr));
}

__device__ __forceinline__ void cp_async16(uint32_t smem_addr, const void* gptr) {
    asm volatile("cp.async.cg.shared.global [%0], [%1], 16;"
                 :: "r"(smem_addr), "l"(gptr) : "memory");
}
__device__ __forceinline__ void cp_commit() {
    asm volatile("cp.async.commit_group;" ::: "memory");
}
__device__ __forceinline__ void cp_wait0() {
    asm volatile("cp.async.wait_group 0;" ::: "memory");
}

// ---------------------------------------------------------------------------
// TF32 mma.sync GEMM NT (unchanged from R5/R6, validated).
// ---------------------------------------------------------------------------
#define GA_W 20

__global__ __launch_bounds__(256, 2) void gemm_mma(const float* __restrict__ A,
                                                   const float* __restrict__ Bm,
                                                   float* __restrict__ C,
                                                   int M, int Nn, int K)
{
    __shared__ uint32_t As[2][128 * GA_W];
    __shared__ uint32_t Bs[2][128 * GA_W];

    const int tid = threadIdx.x;
    const int w = tid >> 5, lane = tid & 31;
    const int wr = w >> 2;
    const int wc = w & 3;
    const int g = lane >> 2;
    const int tg = lane & 3;
    const int rowBase = blockIdx.y * 128;
    const int colBase = blockIdx.x * 128;
    const float* Ag = A + (size_t)rowBase * K;
    const float* Bg = Bm + (size_t)colBase * K;

    const uint32_t asB[2] = { (uint32_t)__cvta_generic_to_shared(As[0]),
                              (uint32_t)__cvta_generic_to_shared(As[1]) };
    const uint32_t bsB[2] = { (uint32_t)__cvta_generic_to_shared(Bs[0]),
                              (uint32_t)__cvta_generic_to_shared(Bs[1]) };

    const int aRow = lane & 15;
    const int aCol = 4 * (lane >> 4);
    const int bRow = (lane & 7) + 8 * ((lane >> 4) & 1);
    const int bCol = 4 * ((lane >> 3) & 1);

    const int r0l = tid >> 2, c0l = (tid & 3) << 2;
    const int r1l = (tid + 256) >> 2, c1l = ((tid + 256) & 3) << 2;

    float c[4][4][4];
#pragma unroll
    for (int i = 0; i < 4; i++)
#pragma unroll
        for (int j = 0; j < 4; j++)
#pragma unroll
            for (int r = 0; r < 4; r++) c[i][j][r] = 0.f;

    auto cvt_store = [&](int buf, const float4& av0, const float4& av1,
                         const float4& bv0, const float4& bv1) {
        uint32_t* Ad = As[buf];
        uint32_t* Bd = Bs[buf];
        uint4 t;
        t.x = f2tf32(av0.x); t.y = f2tf32(av0.y); t.z = f2tf32(av0.z); t.w = f2tf32(av0.w);
        *(uint4*)&Ad[r0l * GA_W + c0l] = t;
        t.x = f2tf32(av1.x); t.y = f2tf32(av1.y); t.z = f2tf32(av1.z); t.w = f2tf32(av1.w);
        *(uint4*)&Ad[r1l * GA_W + c1l] = t;
        t.x = f2tf32(bv0.x); t.y = f2tf32(bv0.y); t.z = f2tf32(bv0.z); t.w = f2tf32(bv0.w);
        *(uint4*)&Bd[r0l * GA_W + c0l] = t;
        t.x = f2tf32(bv1.x); t.y = f2tf32(bv1.y); t.z = f2tf32(bv1.z); t.w = f2tf32(bv1.w);
        *(uint4*)&Bd[r1l * GA_W + c1l] = t;
    };

    {
        float4 a0 = *(const float4*)(Ag + (size_t)r0l * K + c0l);
        float4 a1 = *(const float4*)(Ag + (size_t)r1l * K + c1l);
        float4 b0 = *(const float4*)(Bg + (size_t)r0l * K + c0l);
        float4 b1 = *(const float4*)(Bg + (size_t)r1l * K + c1l);
        cvt_store(0, a0, a1, b0, b1);
    }
    __syncthreads();

    const int nChunks = K >> 4;
    for (int ck = 0; ck < nChunks; ck++) {
        const int buf = ck & 1;
        float4 av0, av1, bv0, bv1;
        const bool more = (ck + 1 < nChunks);
        if (more) {
            const int k0 = (ck + 1) << 4;
            av0 = *(const float4*)(Ag + (size_t)r0l * K + k0 + c0l);
            av1 = *(const float4*)(Ag + (size_t)r1l * K + k0 + c1l);
            bv0 = *(const float4*)(Bg + (size_t)r0l * K + k0 + c0l);
            bv1 = *(const float4*)(Bg + (size_t)r1l * K + k0 + c1l);
        }

#pragma unroll
        for (int ks = 0; ks < 2; ks++) {
            const int kb = ks * 8;
            uint32_t a[4][4], b[4][2];
#pragma unroll
            for (int i = 0; i < 4; i++) {
                const int row = wr * 64 + i * 16 + aRow;
                ldsm_x4(a[i][0], a[i][1], a[i][2], a[i][3],
                        asB[buf] + (row * GA_W + kb + aCol) * 4);
            }
#pragma unroll
            for (int jp = 0; jp < 2; jp++) {
                const int row = wc * 32 + jp * 16 + bRow;
                ldsm_x4(b[2 * jp][0], b[2 * jp][1], b[2 * jp + 1][0], b[2 * jp + 1][1],
                        bsB[buf] + (row * GA_W + kb + bCol) * 4);
            }
#pragma unroll
            for (int i = 0; i < 4; i++)
#pragma unroll
                for (int j = 0; j < 4; j++)
                    mma_tf32(c[i][j], a[i], b[j]);
        }

        if (more) cvt_store(buf ^ 1, av0, av1, bv0, bv1);
        __syncthreads();
    }

#pragma unroll
    for (int i = 0; i < 4; i++) {
        const int r0 = rowBase + wr * 64 + i * 16 + g;
#pragma unroll
        for (int j = 0; j < 4; j++) {
            const int cl = colBase + wc * 32 + j * 8 + 2 * tg;
            *(float2*)(C + (size_t)r0 * Nn + cl)       = make_float2(c[i][j][0], c[i][j][1]);
            *(float2*)(C + (size_t)(r0 + 8) * Nn + cl) = make_float2(c[i][j][2], c[i][j][3]);
        }
    }
}

// ---------------------------------------------------------------------------
// Tensorized flash attention (tf32 mma.sync), cp.async double-buffered K/V.
// smem: buf[2] of [K 64x72 | V 64x72] (raw fp32 from cp.async, cvt'd in
// place to tf32), Ps[8][16][68] P staging. Q staged through buf0.
// ---------------------------------------------------------------------------
#define KS_W 72
#define PS_W 68
#define BUF_WORDS (2 * 64 * KS_W)                 // 9216 (K + V)
#define FA3_WORDS (2 * BUF_WORDS + 8 * 16 * PS_W) // 27136
#define FA3_SMEM (FA3_WORDS * 4)                  // 108544 B

__global__ __launch_bounds__(256, 2) void flash_mma(const float* __restrict__ qkv,
                                                    const float* __restrict__ bias,
                                                    const float* __restrict__ beta,
                                                    float* __restrict__ out)
{
    extern __shared__ uint32_t sm2[];
    uint32_t* Ps = sm2 + 2 * BUF_WORDS;

    const int tid = threadIdx.x;
    const int w = tid >> 5, lane = tid & 31;
    const int g = lane >> 2, tg = lane & 3;
    const int b = blockIdx.y >> 4, h = blockIdx.y & 15;
    const int q0 = blockIdx.x * 128;

    const uint32_t smBase = (uint32_t)__cvta_generic_to_shared(sm2);
    const uint32_t pwBase = (uint32_t)__cvta_generic_to_shared(Ps + w * 16 * PS_W);

    const float* qbase = qkv + ((size_t)b * NN + q0) * QKV_COLS + h * DH;
    const float* kbase = qkv + ((size_t)b * NN) * QKV_COLS + DM + h * DH;
    const float* vbase = qkv + ((size_t)b * NN) * QKV_COLS + 2 * DM + h * DH;

    // Per-thread load geometry (4 segments of 16B per matrix per tile)
    const int ldRow[4] = { tid >> 4, (tid + 256) >> 4, (tid + 512) >> 4, (tid + 768) >> 4 };
    const int ldC4[4]  = { (tid & 15) << 2, ((tid + 256) & 15) << 2,
                           ((tid + 512) & 15) << 2, ((tid + 768) & 15) << 2 };

    // ---- Stage Q (x 1/8, tf32, swizzled) through buf0 area, into registers ----
    {
        uint32_t* Qst = sm2;               // [128][72]
        for (int f = tid; f < 128 * 16; f += 256) {
            int row = f >> 4;
            int c4 = (f & 15) << 2;
            float4 v = *(const float4*)(qbase + (size_t)row * QKV_COLS + c4);
            int swz = ((row >> 2) & 1) << 2;
            uint4 t;
            t.x = f2tf32(v.x * 0.125f); t.y = f2tf32(v.y * 0.125f);
            t.z = f2tf32(v.z * 0.125f); t.w = f2tf32(v.w * 0.125f);
            *(uint4*)&Qst[row * KS_W + (c4 ^ swz)] = t;
        }
        __syncthreads();
    }
    const int qsw = ((g >> 2) & 1) << 2;
    uint32_t q[8][4];
    {
        const uint32_t* Qst = sm2;
        const int r0 = w * 16 + g;
#pragma unroll
        for (int kb8 = 0; kb8 < 8; kb8++) {
            const int k0c = kb8 * 8;
            q[kb8][0] = Qst[r0 * KS_W + ((k0c + tg) ^ qsw)];
            q[kb8][1] = Qst[(r0 + 8) * KS_W + ((k0c + tg) ^ qsw)];
            q[kb8][2] = Qst[r0 * KS_W + ((k0c + tg + 4) ^ qsw)];
            q[kb8][3] = Qst[(r0 + 8) * KS_W + ((k0c + tg + 4) ^ qsw)];
        }
        __syncthreads();
    }

    // Issue cp.async for a tile into buffer `bi`
    auto prefetch_tile = [&](int bi, int j0) {
        const uint32_t kDst = smBase + bi * BUF_WORDS * 4;
        const uint32_t vDst = kDst + 64 * KS_W * 4;
#pragma unroll
        for (int l = 0; l < 4; l++) {
            const int row = ldRow[l], c4 = ldC4[l];
            const int swz = ((row >> 2) & 1) << 2;
            cp_async16(kDst + (row * KS_W + (c4 ^ swz)) * 4,
                       kbase + (size_t)(j0 + row) * QKV_COLS + c4);
            cp_async16(vDst + (row * KS_W + c4) * 4,
                       vbase + (size_t)(j0 + row) * QKV_COLS + c4);
        }
        cp_commit();
    };

    prefetch_tile(0, 0);

    float o[8][4];
#pragma unroll
    for (int j = 0; j < 8; j++)
#pragma unroll
        for (int r = 0; r < 4; r++) o[j][r] = 0.f;
    float m0 = -1e30f, m1 = -1e30f, l0 = 0.f, l1 = 0.f;
    const float betah = (h < NPHYS) ? beta[h] : 0.f;

    const int sRowOff = lane & 7;
    const int sColQ = 4 * (lane >> 3);
    const int swzl = (lane & 4);
    const int pRow = lane & 15;
    const int pCol = 4 * (lane >> 4);

    for (int t32 = 0; t32 < 32; t32++) {
        const int bi = t32 & 1;
        uint32_t* kb = sm2 + bi * BUF_WORDS;     // raw K (swizzled positions)
        uint32_t* vb = kb + 64 * KS_W;           // raw V
        const uint32_t ksBase = smBase + bi * BUF_WORDS * 4;

        cp_wait0();            // this thread's tile t32 copies done
        __syncthreads();       // all threads' copies done; prev compute done

        // Prefetch next tile (targets the other buffer — free since the
        // sync above closed its last readers)
        if (t32 + 1 < 32) prefetch_tile(bi ^ 1, (t32 + 1) * 64);

        // Convert this tile's raw fp32 -> tf32 in place (position-agnostic)
#pragma unroll
        for (int u = 0; u < 9; u++) {
            uint4* p = (uint4*)kb + tid + u * 256;
            uint4 v = *p;
            v.x = f2tf32(__uint_as_float(v.x));
            v.y = f2tf32(__uint_as_float(v.y));
            v.z = f2tf32(__uint_as_float(v.z));
            v.w = f2tf32(__uint_as_float(v.w));
            *p = v;
        }
        __syncthreads();       // cvt visible to all warps

        // ---- S = (Q/8) K^T : B-frags via ldmatrix.x4 ----
        float s[8][4];
#pragma unroll
        for (int j = 0; j < 8; j++)
#pragma unroll
            for (int r = 0; r < 4; r++) s[j][r] = 0.f;
#pragma unroll
        for (int jj = 0; jj < 8; jj++) {
            const int krow = jj * 8 + sRowOff;
#pragma unroll
            for (int kq = 0; kq < 4; kq++) {
                uint32_t b0, b1, b2, b3;
                ldsm_x4(b0, b1, b2, b3,
                        ksBase + (krow * KS_W + ((kq * 16 + sColQ) ^ swzl)) * 4);
                uint32_t bb0[2] = {b0, b1}, bb1[2] = {b2, b3};
                mma_tf32(s[jj], q[2 * kq], bb0);
                mma_tf32(s[jj], q[2 * kq + 1], bb1);
            }
        }

        // ---- bias (first NPHYS heads) ----
        if (h < NPHYS) {
            const int j0 = t32 * 64;
            const float* bp = bias + ((size_t)b * NN + q0 + w * 16 + g) * NN + j0;
#pragma unroll
            for (int jj = 0; jj < 8; jj++) {
                float2 b0 = __ldg((const float2*)(bp + jj * 8 + 2 * tg));
                float2 b1 = __ldg((const float2*)(bp + 8 * NN + jj * 8 + 2 * tg));
                s[jj][0] += betah * b0.x; s[jj][1] += betah * b0.y;
                s[jj][2] += betah * b1.x; s[jj][3] += betah * b1.y;
            }
        }

        // ---- online softmax ----
        float rm0 = -1e30f, rm1 = -1e30f;
#pragma unroll
        for (int jj = 0; jj < 8; jj++) {
            rm0 = fmaxf(rm0, fmaxf(s[jj][0], s[jj][1]));
            rm1 = fmaxf(rm1, fmaxf(s[jj][2], s[jj][3]));
        }
        rm0 = fmaxf(rm0, __shfl_xor_sync(0xffffffffu, rm0, 1));
        rm0 = fmaxf(rm0, __shfl_xor_sync(0xffffffffu, rm0, 2));
        rm1 = fmaxf(rm1, __shfl_xor_sync(0xffffffffu, rm1, 1));
        rm1 = fmaxf(rm1, __shfl_xor_sync(0xffffffffu, rm1, 2));
        const float mn0 = fmaxf(m0, rm0), mn1 = fmaxf(m1, rm1);
        const float c0 = __expf(m0 - mn0), c1 = __expf(m1 - mn1);
        float sum0 = 0.f, sum1 = 0.f;
#pragma unroll
        for (int jj = 0; jj < 8; jj++) {
            s[jj][0] = __expf(s[jj][0] - mn0); sum0 += s[jj][0];
            s[jj][1] = __expf(s[jj][1] - mn0); sum0 += s[jj][1];
            s[jj][2] = __expf(s[jj][2] - mn1); sum1 += s[jj][2];
            s[jj][3] = __expf(s[jj][3] - mn1); sum1 += s[jj][3];
        }
        sum0 += __shfl_xor_sync(0xffffffffu, sum0, 1);
        sum0 += __shfl_xor_sync(0xffffffffu, sum0, 2);
        sum1 += __shfl_xor_sync(0xffffffffu, sum1, 1);
        sum1 += __shfl_xor_sync(0xffffffffu, sum1, 2);
        l0 = l0 * c0 + sum0; m0 = mn0;
        l1 = l1 * c1 + sum1; m1 = mn1;
#pragma unroll
        for (int jj = 0; jj < 8; jj++) {
            o[jj][0] *= c0; o[jj][1] *= c0;
            o[jj][2] *= c1; o[jj][3] *= c1;
        }

        // ---- stage P (tf32), then PV ----
        {
            uint32_t* Pw = Ps + w * 16 * PS_W;
#pragma unroll
            for (int jj = 0; jj < 8; jj++) {
                uint2 hi0 = make_uint2(f2tf32(s[jj][0]), f2tf32(s[jj][1]));
                uint2 hi1 = make_uint2(f2tf32(s[jj][2]), f2tf32(s[jj][3]));
                *(uint2*)&Pw[g * PS_W + jj * 8 + 2 * tg] = hi0;
                *(uint2*)&Pw[(g + 8) * PS_W + jj * 8 + 2 * tg] = hi1;
            }
        }
        __syncwarp();
#pragma unroll
        for (int kb8 = 0; kb8 < 8; kb8++) {
            const int kc = kb8 * 8;
            uint32_t a[4];
            ldsm_x4(a[0], a[1], a[2], a[3],
                    pwBase + (pRow * PS_W + kc + pCol) * 4);
#pragma unroll
            for (int jj = 0; jj < 8; jj++) {
                const int n = jj * 8 + g;
                uint32_t bh[2];
                bh[0] = vb[(kc + tg) * KS_W + n];
                bh[1] = vb[(kc + tg + 4) * KS_W + n];
                mma_tf32(o[jj], a, bh);
            }
        }
        __syncwarp();   // Ps reads done before next iteration's stores
        // (cross-buffer safety handled by the sync at top of next iteration)
    }

    // ---- normalize + store ----
    const float inv0 = 1.f / l0, inv1 = 1.f / l1;
    float* op0 = out + ((size_t)b * NN + q0 + w * 16 + g) * DM + h * DH;
    float* op1 = op0 + (size_t)8 * DM;
#pragma unroll
    for (int jj = 0; jj < 8; jj++) {
        *(float2*)(op0 + jj * 8 + 2 * tg) = make_float2(o[jj][0] * inv0, o[jj][1] * inv0);
        *(float2*)(op1 + jj * 8 + 2 * tg) = make_float2(o[jj][2] * inv1, o[jj][3] * inv1);
    }
}

// ---------------------------------------------------------------------------
extern "C" void kernel_launch(void* const* d_in, const int* in_sizes, int n_in,
                              void* d_out, int out_size)
{
    const float* x     = (const float*)d_in[0];
    const float* bias  = (const float*)d_in[1];
    const float* Wqkv  = (const float*)d_in[2];
    const float* Wproj = (const float*)d_in[3];
    const float* beta  = (const float*)d_in[4];
    float* out = (float*)d_out;

    float *qkv_ptr, *att_ptr;
    cudaGetSymbolAddress((void**)&qkv_ptr, g_qkv);
    cudaGetSymbolAddress((void**)&att_ptr, g_att);

    static bool attr_set = false;
    if (!attr_set) {
        cudaFuncSetAttribute(flash_mma, cudaFuncAttributeMaxDynamicSharedMemorySize, FA3_SMEM);
        attr_set = true;
    }

    // 1) QKV projection (tf32 mma.sync, double-buffered, ldmatrix)
    gemm_mma<<<dim3(QKV_COLS / 128, M_ROWS / 128), 256>>>(x, Wqkv, qkv_ptr,
                                                          M_ROWS, QKV_COLS, DM);

    // 2) Tensorized flash attention (cp.async pipelined)
    flash_mma<<<dim3(NN / 128, BB * HH), 256, FA3_SMEM>>>(qkv_ptr, bias, beta, att_ptr);

    // 3) Output projection (tf32 mma.sync)
    gemm_mma<<<dim3(DM / 128, M_ROWS / 128), 256>>>(att_ptr, Wproj, out,
                                                    M_ROWS, DM, DM);
}